// round 8
// baseline (speedup 1.0000x reference)
#include <cuda_runtime.h>
#include <cuda_fp16.h>
#include <cstdint>

// QuadraticConv2D implicit GEMM, fp16 mma.sync with f16 accumulators promoted
// to fp32 once per feature (per-feature zero-C chain of 4 k16 MMAs).
// M=65536, K=54*64 (+exact fp32 bias), N=64.
// CTA: 256 thr, 128 m rows (2 image rows), warp tile m32n32 (8 warps = m128n64).
// Warp m32 = one image row (irow = wm>>1), w in [wbase, wbase+32).
// Grid 512. x staged fp16 (38KB), W fp16 4-deep cp.async ring (36.9KB).
// NOTE: ring depth MUST exceed prefetch distance (4 > 3) — with 3 buffers the
// prefetch of f+3 aliases the buffer being consumed at f (R6/R7 bug).

#define XS_STRIDE 72                    // halfs per w position (conflict-free)
#define XS_ROW    (66 * XS_STRIDE)      // 4752 halfs per image row
#define XS_HALFS  (4 * XS_ROW)          // 19008
#define WS_OFF    (XS_HALFS * 2)        // 38016 B
#define WS_BUF    9216                  // one W_l block: 64 o x 72 halfs
#define NBUF      4
#define SMEM_BYTES (WS_OFF + NBUF * WS_BUF)   // 74880

__device__ __align__(16) __half Wg[54 * 4608];   // [l][o][c], 72-half stride
__device__ float bvecg[64];                       // exact bias (fp32)

__constant__ unsigned char F_I[54] = {
    0,0,0,0,0,0,0,0,0,0, 1,1,1,1,1,1,1,1,1, 2,2,2,2,2,2,2,2,
    3,3,3,3,3,3,3, 4,4,4,4,4,4, 5,5,5,5,5, 6,6,6,6, 7,7,7, 8,8};
__constant__ unsigned char F_J[54] = {
    0,1,2,3,4,5,6,7,8,255, 1,2,3,4,5,6,7,8,255, 2,3,4,5,6,7,8,255,
    3,4,5,6,7,8,255, 4,5,6,7,8,255, 5,6,7,8,255, 6,7,8,255, 7,8,255, 8,255};
__constant__ unsigned char F_L[54] = {
    0,1,2,3,4,5,6,7,8,45, 9,10,11,12,13,14,15,16,46, 17,18,19,20,21,22,23,47,
    24,25,26,27,28,29,48, 30,31,32,33,34,49, 35,36,37,38,50,
    39,40,41,51, 42,43,52, 44,53};

// m16n8k16, f16 D/C. Zero-C variant starts a fresh per-feature chain.
static __device__ __forceinline__ void mma_h_zero(uint32_t* d,
    uint32_t a0, uint32_t a1, uint32_t a2, uint32_t a3,
    uint32_t b0, uint32_t b1) {
    asm volatile(
        "mma.sync.aligned.m16n8k16.row.col.f16.f16.f16.f16 "
        "{%0,%1}, {%2,%3,%4,%5}, {%6,%7}, {%8,%8};"
        : "=r"(d[0]), "=r"(d[1])
        : "r"(a0), "r"(a1), "r"(a2), "r"(a3), "r"(b0), "r"(b1), "r"(0u));
}
static __device__ __forceinline__ void mma_h_acc(uint32_t* d,
    uint32_t a0, uint32_t a1, uint32_t a2, uint32_t a3,
    uint32_t b0, uint32_t b1) {
    asm volatile(
        "mma.sync.aligned.m16n8k16.row.col.f16.f16.f16.f16 "
        "{%0,%1}, {%2,%3,%4,%5}, {%6,%7}, {%0,%1};"
        : "+r"(d[0]), "+r"(d[1])
        : "r"(a0), "r"(a1), "r"(a2), "r"(a3), "r"(b0), "r"(b1));
}

__global__ void prep_W(const float* __restrict__ wk) {
    const int l = blockIdx.x;
    if (l < 54) {
        for (int idx = threadIdx.x; idx < 4096; idx += 256) {
            const int o = idx >> 6, c = idx & 63;
            Wg[l * 4608 + o * 72 + c] = __float2half_rn(wk[l * 4096 + c * 64 + o]);
        }
    } else if (threadIdx.x < 64) {
        float s = 0.f;
        for (int c = 0; c < 64; ++c) s += wk[54 * 4096 + c * 64 + threadIdx.x];
        bvecg[threadIdx.x] = s;
    }
}

static __device__ __forceinline__ void issue_w_cp(uint32_t dst, int l, int t) {
    const char* src = (const char*)Wg + (size_t)F_L[l] * WS_BUF;
    asm volatile("cp.async.ca.shared.global [%0], [%1], 16;"
                 :: "r"(dst + t * 16), "l"(src + t * 16) : "memory");
    asm volatile("cp.async.ca.shared.global [%0], [%1], 16;"
                 :: "r"(dst + (t + 256) * 16), "l"(src + (t + 256) * 16) : "memory");
    if (t < 64)
        asm volatile("cp.async.ca.shared.global [%0], [%1], 16;"
                     :: "r"(dst + (t + 512) * 16), "l"(src + (t + 512) * 16) : "memory");
    asm volatile("cp.async.commit_group;" ::: "memory");
}

__global__ __launch_bounds__(256, 2)
void qconv_mma(const float* __restrict__ x, float* __restrict__ out) {
    extern __shared__ __half xsm[];
    __half* xs = xsm;
    const uint32_t smem_base = (uint32_t)__cvta_generic_to_shared(xsm);
    const uint32_t wsB = smem_base + WS_OFF;

    const int t    = threadIdx.x;
    const int warp = t >> 5, lane = t & 31;
    const int r    = lane >> 2, t4 = lane & 3;
    const int wm   = warp >> 1;          // 0..3 -> m32 block
    const int wn   = warp & 1;           // 0..1 -> n32 block
    const int mbase = wm * 32;
    const int irow  = wm >> 1;           // image row within CTA (0..1)
    const int wbase = (wm & 1) * 32;     // w offset within image row
    const int bb = blockIdx.x >> 5;
    const int r0 = (blockIdx.x & 31) * 2;

    // ---- stage 4 x-rows as fp16 (stride-72, zero halo) ----
    #pragma unroll
    for (int rr = 0; rr < 4; ++rr) {
        const int hh = r0 + rr - 1;
        if (hh >= 0 && hh < 64) {
            const float4* src = (const float4*)(x + (size_t)(bb * 64 + hh) * 4096);
            #pragma unroll
            for (int k = 0; k < 4; ++k) {
                const int idx = t + k * 256;          // float4 idx 0..1023
                const int ww = idx >> 4, c4 = idx & 15;
                const float4 v = src[idx];
                const __half2 h0 = __floats2half2_rn(v.x, v.y);
                const __half2 h1 = __floats2half2_rn(v.z, v.w);
                uint2 pk;
                pk.x = *(const uint32_t*)&h0;
                pk.y = *(const uint32_t*)&h1;
                *(uint2*)(xs + rr * XS_ROW + (ww + 1) * XS_STRIDE + c4 * 4) = pk;
            }
        } else {
            const uint2 z = make_uint2(0u, 0u);
            #pragma unroll
            for (int k = 0; k < 4; ++k) {
                const int idx = t + k * 256;
                const int ww = idx >> 4, c4 = idx & 15;
                *(uint2*)(xs + rr * XS_ROW + (ww + 1) * XS_STRIDE + c4 * 4) = z;
            }
        }
    }
    if (t < 128) {
        const int rr = t >> 5, side = (t >> 4) & 1, c4 = t & 15;
        *(uint2*)(xs + rr * XS_ROW + (side ? 65 : 0) * XS_STRIDE + c4 * 4) =
            make_uint2(0u, 0u);
    }

    issue_w_cp(wsB + 0 * WS_BUF, 0, t);
    issue_w_cp(wsB + 1 * WS_BUF, 1, t);
    issue_w_cp(wsB + 2 * WS_BUF, 2, t);

    float acc[2][4][4];                  // [m16 blk][nt][4]
    #pragma unroll
    for (int a = 0; a < 2; ++a)
        #pragma unroll
        for (int b = 0; b < 4; ++b)
            #pragma unroll
            for (int cc = 0; cc < 4; ++cc) acc[a][b][cc] = 0.f;

    uint32_t xi[4][8];                   // tap-i cache: 4 m-positions x 8 half2
    int cur_i = -1;

    for (int f = 0; f < 54; ++f) {
        if (f < 52)       asm volatile("cp.async.wait_group 2;" ::: "memory");
        else if (f == 52) asm volatile("cp.async.wait_group 1;" ::: "memory");
        else              asm volatile("cp.async.wait_group 0;" ::: "memory");
        __syncthreads();    // W[f] visible; buffer (f+3)&3 fully consumed at f-1

        if (f + 3 < 54) issue_w_cp(wsB + ((f + 3) & 3) * WS_BUF, f + 3, t);

        const int ii = F_I[f], jj = F_J[f];

        if (ii != cur_i) {
            cur_i = ii;
            const int di = ii / 3, dj = ii % 3;
            #pragma unroll
            for (int mi = 0; mi < 4; ++mi) {
                const __half* base = xs + (irow + di) * XS_ROW
                                   + (wbase + mi * 8 + r + dj) * XS_STRIDE + 2 * t4;
                #pragma unroll
                for (int p = 0; p < 8; ++p)
                    xi[mi][p] = *(const uint32_t*)(base + 8 * p);
            }
        }

        const char* wbuf = (const char*)xs + WS_OFF + (f & 3) * WS_BUF
                         + wn * 32 * 144;
        const bool quad = (jj != 255);
        const __half* jb[4];
        if (quad) {
            const int dr = jj / 3, dc = jj % 3;
            #pragma unroll
            for (int mi = 0; mi < 4; ++mi)
                jb[mi] = xs + (irow + dr) * XS_ROW
                       + (wbase + mi * 8 + r + dc) * XS_STRIDE + 2 * t4;
        }

        uint32_t dfr[2][4][2];           // f16 D frags for this feature

        #pragma unroll
        for (int q = 0; q < 4; ++q) {
            uint32_t b0[4], b1[4];
            #pragma unroll
            for (int nt = 0; nt < 4; ++nt) {
                const char* ad = wbuf + (nt * 8 + r) * 144 + q * 32 + t4 * 4;
                b0[nt] = *(const uint32_t*)ad;
                b1[nt] = *(const uint32_t*)(ad + 16);
            }
            uint32_t ha[4][2];
            #pragma unroll
            for (int mi = 0; mi < 4; ++mi) {
                if (quad) {
                    const uint32_t j0 = *(const uint32_t*)(jb[mi] + 16 * q);
                    const uint32_t j1 = *(const uint32_t*)(jb[mi] + 16 * q + 8);
                    const __half2 p0 = __hmul2(*(const __half2*)&xi[mi][2 * q],
                                               *(const __half2*)&j0);
                    const __half2 p1 = __hmul2(*(const __half2*)&xi[mi][2 * q + 1],
                                               *(const __half2*)&j1);
                    ha[mi][0] = *(const uint32_t*)&p0;
                    ha[mi][1] = *(const uint32_t*)&p1;
                } else {
                    ha[mi][0] = xi[mi][2 * q];
                    ha[mi][1] = xi[mi][2 * q + 1];
                }
            }
            if (q == 0) {
                #pragma unroll
                for (int nt = 0; nt < 4; ++nt) {
                    mma_h_zero(dfr[0][nt], ha[0][0], ha[1][0], ha[0][1], ha[1][1],
                               b0[nt], b1[nt]);
                    mma_h_zero(dfr[1][nt], ha[2][0], ha[3][0], ha[2][1], ha[3][1],
                               b0[nt], b1[nt]);
                }
            } else {
                #pragma unroll
                for (int nt = 0; nt < 4; ++nt) {
                    mma_h_acc(dfr[0][nt], ha[0][0], ha[1][0], ha[0][1], ha[1][1],
                              b0[nt], b1[nt]);
                    mma_h_acc(dfr[1][nt], ha[2][0], ha[3][0], ha[2][1], ha[3][1],
                              b0[nt], b1[nt]);
                }
            }
        }

        // promote this feature's f16 result into fp32 accumulators
        #pragma unroll
        for (int mb = 0; mb < 2; ++mb)
            #pragma unroll
            for (int nt = 0; nt < 4; ++nt) {
                const float2 lo = __half22float2(*(const __half2*)&dfr[mb][nt][0]);
                const float2 hi = __half22float2(*(const __half2*)&dfr[mb][nt][1]);
                acc[mb][nt][0] += lo.x;
                acc[mb][nt][1] += lo.y;
                acc[mb][nt][2] += hi.x;
                acc[mb][nt][3] += hi.y;
            }
    }

    // ---- epilogue: exact bias add + float2 stores ----
    const int mrow0 = blockIdx.x * 128 + mbase + r;
    #pragma unroll
    for (int mb = 0; mb < 2; ++mb) {
        #pragma unroll
        for (int nt = 0; nt < 4; ++nt) {
            const int n = wn * 32 + nt * 8 + t4 * 2;
            const float bvx = bvecg[n], bvy = bvecg[n + 1];
            float* o0 = out + (size_t)(mrow0 + mb * 16) * 64 + n;
            *(float2*)o0 = make_float2(acc[mb][nt][0] + bvx, acc[mb][nt][1] + bvy);
            *(float2*)(o0 + 8 * 64) =
                make_float2(acc[mb][nt][2] + bvx, acc[mb][nt][3] + bvy);
        }
    }
}

extern "C" void kernel_launch(void* const* d_in, const int* in_sizes, int n_in,
                              void* d_out, int out_size) {
    const float* x  = (const float*)d_in[0];
    const float* wk = (const float*)d_in[1];   // [55,64,64] (l,c,o) contiguous
    float* out = (float*)d_out;

    prep_W<<<55, 256>>>(wk);
    cudaFuncSetAttribute(qconv_mma,
                         cudaFuncAttributeMaxDynamicSharedMemorySize, SMEM_BYTES);
    qconv_mma<<<512, 256, SMEM_BYTES>>>(x, out);
}